// round 12
// baseline (speedup 1.0000x reference)
#include <cuda_runtime.h>
#include <cuda_bf16.h>
#include <math.h>
#include <stdint.h>

#define NW 6

// W: real 128x128 bf16, row-major. Row n<64 -> br_n weights; row 64+n -> bi_n.
__device__ __align__(16) __nv_bfloat16 d_W[128 * 128];

// ---------------- complex helpers ----------------
__device__ __forceinline__ float2 cmul(float2 a, float2 b) {
    return make_float2(a.x * b.x - a.y * b.y, a.x * b.y + a.y * b.x);
}
__device__ __forceinline__ float2 cadd(float2 a, float2 b) {
    return make_float2(a.x + b.x, a.y + b.y);
}
__device__ __forceinline__ float2 cscale(float2 a, float s) {
    return make_float2(a.x * s, a.y * s);
}
__device__ __forceinline__ float2 shflxor(float2 v, int m) {
    v.x = __shfl_xor_sync(0xffffffffu, v.x, m);
    v.y = __shfl_xor_sync(0xffffffffu, v.y, m);
    return v;
}

// ================= build_W (64 blocks x 32 threads) =================
__device__ __forceinline__ void apply_diag(float2& s0, float2& s1, int lane, int w,
                                           float2 d0, float2 d1) {
    int bit = 5 - w;
    if (bit == 0) {
        s0 = cmul(s0, d0);
        s1 = cmul(s1, d1);
    } else {
        int mb = (lane >> (bit - 1)) & 1;
        float2 d = mb ? d1 : d0;
        s0 = cmul(s0, d);
        s1 = cmul(s1, d);
    }
}

__device__ __forceinline__ void apply1(float2& s0, float2& s1, int lane, int w,
                                       float2 u00, float2 u01, float2 u10, float2 u11) {
    int bit = 5 - w;
    if (bit == 0) {
        float2 t0 = cadd(cmul(u00, s0), cmul(u01, s1));
        float2 t1 = cadd(cmul(u10, s0), cmul(u11, s1));
        s0 = t0; s1 = t1;
    } else {
        int lm = 1 << (bit - 1);
        float2 p0 = shflxor(s0, lm);
        float2 p1 = shflxor(s1, lm);
        int mb = (lane >> (bit - 1)) & 1;
        if (mb == 0) {
            s0 = cadd(cmul(u00, s0), cmul(u01, p0));
            s1 = cadd(cmul(u00, s1), cmul(u01, p1));
        } else {
            s0 = cadd(cmul(u10, p0), cmul(u11, s0));
            s1 = cadd(cmul(u10, p1), cmul(u11, s1));
        }
    }
}

__device__ __forceinline__ float2 bsu(float2 s, float2 p, int na, int nb,
                                      float c, float sn, float c2, float ex, float ey) {
    if (na == nb) return na ? cscale(s, c2) : s;
    if (na == 0) {
        return make_float2(c * s.x + sn * (ex * p.x - ey * p.y),
                           c * s.y + sn * (ex * p.y + ey * p.x));
    } else {
        return make_float2(c * s.x - sn * (ex * p.x + ey * p.y),
                           c * s.y - sn * (ex * p.y - ey * p.x));
    }
}

__device__ __forceinline__ void apply_bs(float2& s0, float2& s1, int lane, int w,
                                         float th, float ph) {
    float c, sn;
    __sincosf(th, &sn, &c);
    float c2 = c * c - sn * sn;
    float ex, ey;
    __sincosf(ph, &ey, &ex);
    int ba = 5 - w, bb = 4 - w;
    float2 p0, p1;
    if (bb >= 1) {
        int lm = ((1 << ba) | (1 << bb)) >> 1;
        p0 = shflxor(s0, lm);
        p1 = shflxor(s1, lm);
    } else {
        p0 = shflxor(s1, 1);
        p1 = shflxor(s0, 1);
    }
    int n0 = lane * 2, n1 = lane * 2 + 1;
    s0 = bsu(s0, p0, (n0 >> ba) & 1, (n0 >> bb) & 1, c, sn, c2, ex, ey);
    s1 = bsu(s1, p1, (n1 >> ba) & 1, (n1 >> bb) & 1, c, sn, c2, ex, ey);
}

__global__ void build_W_kernel(const float* __restrict__ var) {
    int col = blockIdx.x;
    int lane = threadIdx.x;
    float2 s0 = make_float2(0.f, 0.f), s1 = make_float2(0.f, 0.f);
    if (lane * 2 == col) s0.x = 1.f;
    if (lane * 2 + 1 == col) s1.x = 1.f;

    for (int l = 0; l < 2; l++) {
        const float* v = var + 50 * l;
        for (int i = 0; i < 5; i++)
            apply_bs(s0, s1, lane, i, __ldg(v + 2 * i), __ldg(v + 2 * i + 1));
        for (int w = 0; w < NW; w++) {
            float ph = __ldg(v + 10 + w);
            float sp, cp; __sincosf(ph, &sp, &cp);
            apply_diag(s0, s1, lane, w, make_float2(1.f, 0.f), make_float2(cp, sp));
        }
        for (int w = 0; w < NW; w++) {
            float r = __ldg(v + 16 + w);
            float e = __expf(r);
            float sech = __fdividef(2.f * e, fmaf(e, e, 1.f));
            float sr = sqrtf(sech);
            apply_diag(s0, s1, lane, w, make_float2(sr, 0.f), make_float2(sech * sr, 0.f));
        }
        for (int i = 0; i < 5; i++)
            apply_bs(s0, s1, lane, i, __ldg(v + 22 + 2 * i), __ldg(v + 23 + 2 * i));
        for (int w = 0; w < NW; w++) {
            float ph = __ldg(v + 32 + w);
            float sp, cp; __sincosf(ph, &sp, &cp);
            apply_diag(s0, s1, lane, w, make_float2(1.f, 0.f), make_float2(cp, sp));
        }
        for (int w = 0; w < NW; w++) {
            float r = __ldg(v + 38 + w);
            float pref = __expf(-0.5f * r * r);
            apply1(s0, s1, lane, w,
                   make_float2(pref, 0.f), make_float2(-pref * r, 0.f),
                   make_float2(pref * r, 0.f), make_float2(pref * (1.f - r * r), 0.f));
        }
        for (int w = 0; w < NW; w++) {
            float ph = __ldg(v + 44 + w);
            float sp, cp; __sincosf(ph, &sp, &cp);
            apply_diag(s0, s1, lane, w, make_float2(1.f, 0.f), make_float2(cp, sp));
        }
    }
    int k = col;
#pragma unroll
    for (int h = 0; h < 2; h++) {
        float2 u = h ? s1 : s0;
        int r = 2 * lane + h;
        d_W[r * 128 + k]              = __float2bfloat16(u.x);
        d_W[r * 128 + 64 + k]         = __float2bfloat16(-u.y);
        d_W[(64 + r) * 128 + k]       = __float2bfloat16(u.y);
        d_W[(64 + r) * 128 + 64 + k]  = __float2bfloat16(u.x);
    }
}

// ================= main fused kernel =================
// 256 threads/CTA, 128 samples/CTA, 8 warps x 16 samples, 3 CTAs/SM.
// Two-pass N-split GEMM (pass0 = br rows 0..63, pass1 = bi rows 64..127),
// br^2 staged through the thread's own out row (L1-resident round trip).
// smem: A 128x136 bf16 [0,34816) ; Ws 128x136 bf16 [34816,69632) ; gb 128 f32.

static constexpr int AS = 136;                        // row stride, bf16 units
static constexpr uint32_t W_OFF  = 128u * AS * 2u;    // 34816
static constexpr uint32_t GB_OFF = W_OFF * 2u;        // 69632
static constexpr uint32_t SMEM_DYN = GB_OFF + 512u;   // 70144

__device__ __forceinline__ void mma16816(float c[4], uint32_t a0, uint32_t a1,
                                         uint32_t a2, uint32_t a3,
                                         uint32_t b0, uint32_t b1) {
    asm("mma.sync.aligned.m16n8k16.row.col.f32.bf16.bf16.f32 "
        "{%0,%1,%2,%3}, {%4,%5,%6,%7}, {%8,%9}, {%0,%1,%2,%3};"
        : "+f"(c[0]), "+f"(c[1]), "+f"(c[2]), "+f"(c[3])
        : "r"(a0), "r"(a1), "r"(a2), "r"(a3), "r"(b0), "r"(b1));
}

__device__ __forceinline__ void ldmx4(uint32_t r[4], uint32_t addr) {
    asm volatile("ldmatrix.sync.aligned.m8n8.x4.shared.b16 {%0,%1,%2,%3}, [%4];"
                 : "=r"(r[0]), "=r"(r[1]), "=r"(r[2]), "=r"(r[3]) : "r"(addr));
}

__global__ void __launch_bounds__(256, 3)
ffb_mma_kernel(const float* __restrict__ x,
               const float* __restrict__ gamma_, const float* __restrict__ beta_,
               float* __restrict__ out, int nsamp) {
    extern __shared__ __align__(16) unsigned char dsm[];
    __nv_bfloat16* As = (__nv_bfloat16*)(dsm);
    __nv_bfloat16* Ws = (__nv_bfloat16*)(dsm + W_OFF);
    float* gb         = (float*)(dsm + GB_OFF);

    int tid  = threadIdx.x;
    int wid  = tid >> 5;
    int lane = tid & 31;
    int g    = lane >> 2;
    int t4   = lane & 3;

    // ---- stage W (coalesced) into padded Ws ----
    {
        const float4* src = (const float4*)d_W;
#pragma unroll
        for (int i = 0; i < 8; i++) {
            int e = tid + 256 * i;
            int row = e >> 4, c = e & 15;
            *(float4*)(Ws + row * AS + c * 8) = __ldg(src + e);
        }
    }
    if (tid < 16)      ((float4*)gb)[tid] = ((const float4*)gamma_)[tid];
    else if (tid < 32) ((float4*)gb)[tid] = ((const float4*)beta_)[tid - 16];

    // ---- prologue (tid<128): amplitudes from global x -> A row tid ----
    if (tid < 128) {
        int s = blockIdx.x * 128 + tid;
        int srd = s < nsamp ? s : (nsamp - 1);
        const float* xr = x + (size_t)srd * 64;
        float2 P3[8], Q3[8];

#pragma unroll
        for (int hf = 0; hf < 2; hf++) {
            int wb = 3 * hf;
            float e2v[3], qv[3], rdv[3];
            float2 cs[3];
            float Pp = 1.f, Ep = 1.f, rdsq = 0.f;
#pragma unroll
            for (int i = 0; i < 3; i++) {
                int w = wb + i;
                float r1   = __ldg(xr + 2 * w);
                float2 dd  = __ldg((const float2*)(xr + 28 + 2 * w));  // (rd, phid)
                float phik = __ldg(xr + 40 + w);
                float r2   = __ldg(xr + 46 + 2 * w);
                float phir = __ldg(xr + 58 + w);
                float e1 = __expf(r1);
                float e2 = __expf(r2);
                e2v[i] = e2;
                qv[i] = fmaf(e2, e2, 1.f);
                Pp *= fmaf(e1, e1, 1.f);
                Ep *= e1 * e2;
                rdv[i] = dd.x;
                rdsq = fmaf(dd.x, dd.x, rdsq);
                float th = dd.y + phik + phir;
                float sth, cth;
                __sincosf(th, &sth, &cth);
                cs[i] = make_float2(cth, sth);
            }
            float prefH = __expf(-0.5f * rdsq);
            float Qp = qv[0] * qv[1] * qv[2];
            float rQ  = __fdividef(1.f, Qp);
            float rPQ = __fdividef(1.f, Pp * Qp);
            float sH = 64.f * Ep * rPQ;                  // prod sech1*sech2
            float AH = prefH * sqrtf(sH);
            float2 T0 = cscale(cs[0], rdv[0] * 2.f * e2v[0] * qv[1] * qv[2] * rQ);
            float2 T1 = cscale(cs[1], rdv[1] * 2.f * e2v[1] * qv[0] * qv[2] * rQ);
            float2 T2 = cscale(cs[2], rdv[2] * 2.f * e2v[2] * qv[0] * qv[1] * rQ);

            float2* H = hf ? Q3 : P3;
            H[0] = make_float2(AH, 0.f);
            H[1] = cscale(T2, AH);
            H[2] = cscale(T1, AH);
            H[3] = cmul(H[2], T2);
            H[4] = cscale(T0, AH);
            H[5] = cmul(H[4], T2);
            H[6] = cmul(H[4], T1);
            H[7] = cmul(H[6], T2);
        }

        __nv_bfloat16* arow = As + tid * AS;
        int stag = lane >> 3;   // conflict-free stagger
#pragma unroll
        for (int i = 0; i < 32; i++) {
            int j0 = (i + stag) & 31;
            int ja = 2 * j0, jb = 2 * j0 + 1;
            float2 aa = cmul(P3[ja >> 3], Q3[ja & 7]);
            float2 ab = cmul(P3[jb >> 3], Q3[jb & 7]);
            *(__nv_bfloat162*)(arow + 2 * j0) =
                __nv_bfloat162(__float2bfloat16(aa.x), __float2bfloat16(ab.x));
            *(__nv_bfloat162*)(arow + 64 + 2 * j0) =
                __nv_bfloat162(__float2bfloat16(aa.y), __float2bfloat16(ab.y));
        }
    }
    __syncthreads();

    int warpM = wid * 16;
    int blockBase = blockIdx.x * 128;

    uint32_t asBase = (uint32_t)__cvta_generic_to_shared(As);
    uint32_t wsBase = (uint32_t)__cvta_generic_to_shared(Ws);
    uint32_t aAddr = asBase + (uint32_t)(((warpM + (lane & 15)) * AS + ((lane >> 4) << 3)) * 2);
    uint32_t bAddr = wsBase + (uint32_t)(((((lane & 7) + ((lane >> 4) << 3)) * AS) +
                                          (((lane >> 3) & 1) << 3)) * 2);

    // ---- pass 0: br half (W rows 0..63) ----
    {
        float c[8][4];
#pragma unroll
        for (int nt = 0; nt < 8; nt++)
#pragma unroll
            for (int e = 0; e < 4; e++) c[nt][e] = 0.f;

#pragma unroll
        for (int ko = 0; ko < 8; ko++) {
            uint32_t a[4];
            ldmx4(a, aAddr + (uint32_t)(ko * 32));
#pragma unroll
            for (int n4 = 0; n4 < 4; n4++) {
                uint32_t b[4];
                ldmx4(b, bAddr + (uint32_t)(n4 * 16 * AS * 2 + ko * 32));
                mma16816(c[n4 * 2],     a[0], a[1], a[2], a[3], b[0], b[1]);
                mma16816(c[n4 * 2 + 1], a[0], a[1], a[2], a[3], b[2], b[3]);
            }
        }
        // stash br^2 in this thread's own out rows (temp)
#pragma unroll
        for (int half = 0; half < 2; half++) {
            int row = blockBase + warpM + g + half * 8;
            if (row < nsamp) {
                float* orow = out + (size_t)row * 64;
#pragma unroll
                for (int nt = 0; nt < 8; nt++) {
                    int j = nt * 8 + t4 * 2;
                    float b0 = c[nt][half * 2 + 0];
                    float b1 = c[nt][half * 2 + 1];
                    *(float2*)(orow + j) = make_float2(b0 * b0, b1 * b1);
                }
            }
        }
    }

    // ---- pass 1: bi half (W rows 64..127) + epilogue ----
    {
        float c[8][4];
#pragma unroll
        for (int nt = 0; nt < 8; nt++)
#pragma unroll
            for (int e = 0; e < 4; e++) c[nt][e] = 0.f;

        uint32_t bAddr1 = bAddr + (uint32_t)(64 * AS * 2);
#pragma unroll
        for (int ko = 0; ko < 8; ko++) {
            uint32_t a[4];
            ldmx4(a, aAddr + (uint32_t)(ko * 32));
#pragma unroll
            for (int n4 = 0; n4 < 4; n4++) {
                uint32_t b[4];
                ldmx4(b, bAddr1 + (uint32_t)(n4 * 16 * AS * 2 + ko * 32));
                mma16816(c[n4 * 2],     a[0], a[1], a[2], a[3], b[0], b[1]);
                mma16816(c[n4 * 2 + 1], a[0], a[1], a[2], a[3], b[2], b[3]);
            }
        }

        // v = br^2(temp) + bi^2 + x ; LayerNorm ; final store
#pragma unroll
        for (int half = 0; half < 2; half++) {
            int row = blockBase + warpM + g + half * 8;
            int rowc = row < nsamp ? row : (nsamp - 1);
            const float* xrow = x + (size_t)rowc * 64;
            float* orow = out + (size_t)rowc * 64;
            float sum = 0.f, sq = 0.f;
#pragma unroll
            for (int nt = 0; nt < 8; nt++) {
                int j = nt * 8 + t4 * 2;
                float2 tv = *(const float2*)(orow + j);       // own prior write
                float2 xv = __ldg((const float2*)(xrow + j));
                float bi0 = c[nt][half * 2 + 0];
                float bi1 = c[nt][half * 2 + 1];
                float v0 = fmaf(bi0, bi0, tv.x) + xv.x;
                float v1 = fmaf(bi1, bi1, tv.y) + xv.y;
                c[nt][half * 2 + 0] = v0;
                c[nt][half * 2 + 1] = v1;
                sum += v0 + v1;
                sq = fmaf(v0, v0, fmaf(v1, v1, sq));
            }
            sum += __shfl_xor_sync(0xffffffffu, sum, 1);
            sum += __shfl_xor_sync(0xffffffffu, sum, 2);
            sq  += __shfl_xor_sync(0xffffffffu, sq, 1);
            sq  += __shfl_xor_sync(0xffffffffu, sq, 2);
            float mu = sum * (1.f / 64.f);
            float vv = sq * (1.f / 64.f) - mu * mu;
            float rstd = rsqrtf(vv + 1e-5f);
            if (row < nsamp) {
#pragma unroll
                for (int nt = 0; nt < 8; nt++) {
                    int j = nt * 8 + t4 * 2;
                    float2 ov;
                    ov.x = fmaf((c[nt][half * 2 + 0] - mu) * rstd, gb[j],     gb[64 + j]);
                    ov.y = fmaf((c[nt][half * 2 + 1] - mu) * rstd, gb[j + 1], gb[64 + j + 1]);
                    *(float2*)(orow + j) = ov;
                }
            }
        }
    }
}

// ---------------- launch ----------------
extern "C" void kernel_launch(void* const* d_in, const int* in_sizes, int n_in,
                              void* d_out, int out_size) {
    const float* x      = (const float*)d_in[0];
    const float* var    = (const float*)d_in[1];
    const float* gamma_ = (const float*)d_in[2];
    const float* beta_  = (const float*)d_in[3];
    float* out = (float*)d_out;

    int nsamp = in_sizes[0] / 64;

    cudaFuncSetAttribute(ffb_mma_kernel,
                         cudaFuncAttributeMaxDynamicSharedMemorySize, SMEM_DYN);

    build_W_kernel<<<64, 32>>>(var);

    int blocks = (nsamp + 127) / 128;
    ffb_mma_kernel<<<blocks, 256, SMEM_DYN>>>(x, gamma_, beta_, out, nsamp);
}

// round 13
// speedup vs baseline: 1.2372x; 1.2372x over previous
#include <cuda_runtime.h>
#include <cuda_bf16.h>
#include <math.h>
#include <stdint.h>

#define NW 6

// W: real 128x128 bf16, row-major. Row n<64 -> br_n weights; row 64+n -> bi_n.
__device__ __align__(16) __nv_bfloat16 d_W[128 * 128];

// ---------------- complex helpers ----------------
__device__ __forceinline__ float2 cmul(float2 a, float2 b) {
    return make_float2(a.x * b.x - a.y * b.y, a.x * b.y + a.y * b.x);
}
__device__ __forceinline__ float2 cadd(float2 a, float2 b) {
    return make_float2(a.x + b.x, a.y + b.y);
}
__device__ __forceinline__ float2 cscale(float2 a, float s) {
    return make_float2(a.x * s, a.y * s);
}
__device__ __forceinline__ float2 shflxor(float2 v, int m) {
    v.x = __shfl_xor_sync(0xffffffffu, v.x, m);
    v.y = __shfl_xor_sync(0xffffffffu, v.y, m);
    return v;
}

// ================= build_W (64 blocks x 32 threads) =================
__device__ __forceinline__ void apply_diag(float2& s0, float2& s1, int lane, int w,
                                           float2 d0, float2 d1) {
    int bit = 5 - w;
    if (bit == 0) {
        s0 = cmul(s0, d0);
        s1 = cmul(s1, d1);
    } else {
        int mb = (lane >> (bit - 1)) & 1;
        float2 d = mb ? d1 : d0;
        s0 = cmul(s0, d);
        s1 = cmul(s1, d);
    }
}

__device__ __forceinline__ void apply1(float2& s0, float2& s1, int lane, int w,
                                       float2 u00, float2 u01, float2 u10, float2 u11) {
    int bit = 5 - w;
    if (bit == 0) {
        float2 t0 = cadd(cmul(u00, s0), cmul(u01, s1));
        float2 t1 = cadd(cmul(u10, s0), cmul(u11, s1));
        s0 = t0; s1 = t1;
    } else {
        int lm = 1 << (bit - 1);
        float2 p0 = shflxor(s0, lm);
        float2 p1 = shflxor(s1, lm);
        int mb = (lane >> (bit - 1)) & 1;
        if (mb == 0) {
            s0 = cadd(cmul(u00, s0), cmul(u01, p0));
            s1 = cadd(cmul(u00, s1), cmul(u01, p1));
        } else {
            s0 = cadd(cmul(u10, p0), cmul(u11, s0));
            s1 = cadd(cmul(u10, p1), cmul(u11, s1));
        }
    }
}

__device__ __forceinline__ float2 bsu(float2 s, float2 p, int na, int nb,
                                      float c, float sn, float c2, float ex, float ey) {
    if (na == nb) return na ? cscale(s, c2) : s;
    if (na == 0) {
        return make_float2(c * s.x + sn * (ex * p.x - ey * p.y),
                           c * s.y + sn * (ex * p.y + ey * p.x));
    } else {
        return make_float2(c * s.x - sn * (ex * p.x + ey * p.y),
                           c * s.y - sn * (ex * p.y - ey * p.x));
    }
}

__device__ __forceinline__ void apply_bs(float2& s0, float2& s1, int lane, int w,
                                         float th, float ph) {
    float c, sn;
    __sincosf(th, &sn, &c);
    float c2 = c * c - sn * sn;
    float ex, ey;
    __sincosf(ph, &ey, &ex);
    int ba = 5 - w, bb = 4 - w;
    float2 p0, p1;
    if (bb >= 1) {
        int lm = ((1 << ba) | (1 << bb)) >> 1;
        p0 = shflxor(s0, lm);
        p1 = shflxor(s1, lm);
    } else {
        p0 = shflxor(s1, 1);
        p1 = shflxor(s0, 1);
    }
    int n0 = lane * 2, n1 = lane * 2 + 1;
    s0 = bsu(s0, p0, (n0 >> ba) & 1, (n0 >> bb) & 1, c, sn, c2, ex, ey);
    s1 = bsu(s1, p1, (n1 >> ba) & 1, (n1 >> bb) & 1, c, sn, c2, ex, ey);
}

__global__ void build_W_kernel(const float* __restrict__ var) {
    int col = blockIdx.x;
    int lane = threadIdx.x;
    float2 s0 = make_float2(0.f, 0.f), s1 = make_float2(0.f, 0.f);
    if (lane * 2 == col) s0.x = 1.f;
    if (lane * 2 + 1 == col) s1.x = 1.f;

    for (int l = 0; l < 2; l++) {
        const float* v = var + 50 * l;
        for (int i = 0; i < 5; i++)
            apply_bs(s0, s1, lane, i, __ldg(v + 2 * i), __ldg(v + 2 * i + 1));
        for (int w = 0; w < NW; w++) {
            float ph = __ldg(v + 10 + w);
            float sp, cp; __sincosf(ph, &sp, &cp);
            apply_diag(s0, s1, lane, w, make_float2(1.f, 0.f), make_float2(cp, sp));
        }
        for (int w = 0; w < NW; w++) {
            float r = __ldg(v + 16 + w);
            float e = __expf(r);
            float sech = __fdividef(2.f * e, fmaf(e, e, 1.f));
            float sr = sqrtf(sech);
            apply_diag(s0, s1, lane, w, make_float2(sr, 0.f), make_float2(sech * sr, 0.f));
        }
        for (int i = 0; i < 5; i++)
            apply_bs(s0, s1, lane, i, __ldg(v + 22 + 2 * i), __ldg(v + 23 + 2 * i));
        for (int w = 0; w < NW; w++) {
            float ph = __ldg(v + 32 + w);
            float sp, cp; __sincosf(ph, &sp, &cp);
            apply_diag(s0, s1, lane, w, make_float2(1.f, 0.f), make_float2(cp, sp));
        }
        for (int w = 0; w < NW; w++) {
            float r = __ldg(v + 38 + w);
            float pref = __expf(-0.5f * r * r);
            apply1(s0, s1, lane, w,
                   make_float2(pref, 0.f), make_float2(-pref * r, 0.f),
                   make_float2(pref * r, 0.f), make_float2(pref * (1.f - r * r), 0.f));
        }
        for (int w = 0; w < NW; w++) {
            float ph = __ldg(v + 44 + w);
            float sp, cp; __sincosf(ph, &sp, &cp);
            apply_diag(s0, s1, lane, w, make_float2(1.f, 0.f), make_float2(cp, sp));
        }
    }
    int k = col;
#pragma unroll
    for (int h = 0; h < 2; h++) {
        float2 u = h ? s1 : s0;
        int r = 2 * lane + h;
        d_W[r * 128 + k]              = __float2bfloat16(u.x);
        d_W[r * 128 + 64 + k]         = __float2bfloat16(-u.y);
        d_W[(64 + r) * 128 + k]       = __float2bfloat16(u.y);
        d_W[(64 + r) * 128 + 64 + k]  = __float2bfloat16(u.x);
    }
}

// ================= main fused kernel =================
// 256 threads/CTA, 128 samples/CTA, 4 warp-PAIRS x 32 samples, 2 CTAs/SM.
// Pair p: even warp computes br half (W rows 0..63), odd warp bi half (64..127),
// both for samples [p*32, p*32+32) (2 M-tiles). bi^2 exchanged via Ex (reuses A region).
// smem: A/Ex 34816 [0,34816) ; Ws 128x136 bf16 [34816,69632) ;
//       Xs 128x65 f32 [69632,102912) ; gb 128 f32 [102912,103424).

static constexpr int AS = 136;                        // row stride, bf16 units
static constexpr uint32_t W_OFF  = 128u * AS * 2u;    // 34816
static constexpr uint32_t X_OFF  = W_OFF * 2u;        // 69632
static constexpr uint32_t GB_OFF = X_OFF + 128u * 65u * 4u;  // 102912
static constexpr uint32_t SMEM_DYN = GB_OFF + 512u;   // 103424

__device__ __forceinline__ void mma16816(float c[4], uint32_t a0, uint32_t a1,
                                         uint32_t a2, uint32_t a3,
                                         uint32_t b0, uint32_t b1) {
    asm("mma.sync.aligned.m16n8k16.row.col.f32.bf16.bf16.f32 "
        "{%0,%1,%2,%3}, {%4,%5,%6,%7}, {%8,%9}, {%0,%1,%2,%3};"
        : "+f"(c[0]), "+f"(c[1]), "+f"(c[2]), "+f"(c[3])
        : "r"(a0), "r"(a1), "r"(a2), "r"(a3), "r"(b0), "r"(b1));
}

__device__ __forceinline__ void ldmx4(uint32_t r[4], uint32_t addr) {
    asm volatile("ldmatrix.sync.aligned.m8n8.x4.shared.b16 {%0,%1,%2,%3}, [%4];"
                 : "=r"(r[0]), "=r"(r[1]), "=r"(r[2]), "=r"(r[3]) : "r"(addr));
}

__global__ void __launch_bounds__(256, 2)
ffb_mma_kernel(const float* __restrict__ x,
               const float* __restrict__ gamma_, const float* __restrict__ beta_,
               float* __restrict__ out, int nsamp) {
    extern __shared__ __align__(16) unsigned char dsm[];
    __nv_bfloat16* As = (__nv_bfloat16*)(dsm);
    float* Ex         = (float*)(dsm);                 // reuses A region after GEMM
    __nv_bfloat16* Ws = (__nv_bfloat16*)(dsm + W_OFF);
    float* Xs         = (float*)(dsm + X_OFF);
    float* gb         = (float*)(dsm + GB_OFF);

    int tid  = threadIdx.x;
    int wid  = tid >> 5;
    int lane = tid & 31;
    int g    = lane >> 2;
    int t4   = lane & 3;
    int pair = wid >> 1;        // 0..3, samples [pair*32, pair*32+32)
    int half = wid & 1;         // 0 = br (W rows 0..63), 1 = bi (rows 64..127)

    // ---- stage x tile (coalesced float4) into padded Xs ----
    {
        const float4* x4 = (const float4*)x;
        size_t tb4 = (size_t)blockIdx.x * 2048;
        size_t lim = (size_t)nsamp * 16;
#pragma unroll
        for (int i = 0; i < 8; i++) {
            int e = tid + 256 * i;
            size_t gaddr = tb4 + e;
            float4 v = (gaddr < lim) ? __ldg(x4 + gaddr) : make_float4(0.f, 0.f, 0.f, 0.f);
            int row = e >> 4, c = (e & 15) * 4;
            float* p = Xs + row * 65 + c;
            p[0] = v.x; p[1] = v.y; p[2] = v.z; p[3] = v.w;
        }
    }
    // ---- stage W (coalesced) into padded Ws ----
    {
        const float4* src = (const float4*)d_W;
#pragma unroll
        for (int i = 0; i < 8; i++) {
            int e = tid + 256 * i;
            int row = e >> 4, c = e & 15;
            *(float4*)(Ws + row * AS + c * 8) = __ldg(src + e);
        }
    }
    if (tid < 16)      ((float4*)gb)[tid] = ((const float4*)gamma_)[tid];
    else if (tid < 32) ((float4*)gb)[tid] = ((const float4*)beta_)[tid - 16];
    __syncthreads();

    // ---- prologue (tid<128): amplitudes from Xs -> A row tid ----
    if (tid < 128) {
        const float* Xrow = Xs + tid * 65;
        float2 P3[8], Q3[8];

#pragma unroll
        for (int hf = 0; hf < 2; hf++) {
            int wb = 3 * hf;
            float e2v[3], qv[3], rdv[3];
            float2 cs[3];
            float Pp = 1.f, Ep = 1.f, rdsq = 0.f;
#pragma unroll
            for (int i = 0; i < 3; i++) {
                int w = wb + i;
                float r1   = Xrow[2 * w];
                float rd   = Xrow[28 + 2 * w];
                float phid = Xrow[29 + 2 * w];
                float phik = Xrow[40 + w];
                float r2   = Xrow[46 + 2 * w];
                float phir = Xrow[58 + w];
                float e1 = __expf(r1);
                float e2 = __expf(r2);
                e2v[i] = e2;
                qv[i] = fmaf(e2, e2, 1.f);
                Pp *= fmaf(e1, e1, 1.f);
                Ep *= e1 * e2;
                rdv[i] = rd;
                rdsq = fmaf(rd, rd, rdsq);
                float th = phid + phik + phir;
                float sth, cth;
                __sincosf(th, &sth, &cth);
                cs[i] = make_float2(cth, sth);
            }
            float prefH = __expf(-0.5f * rdsq);
            float Qp = qv[0] * qv[1] * qv[2];
            float rQ  = __fdividef(1.f, Qp);
            float rPQ = __fdividef(1.f, Pp * Qp);
            float sH = 64.f * Ep * rPQ;                  // prod sech1*sech2
            float AH = prefH * sqrtf(sH);
            float2 T0 = cscale(cs[0], rdv[0] * 2.f * e2v[0] * qv[1] * qv[2] * rQ);
            float2 T1 = cscale(cs[1], rdv[1] * 2.f * e2v[1] * qv[0] * qv[2] * rQ);
            float2 T2 = cscale(cs[2], rdv[2] * 2.f * e2v[2] * qv[0] * qv[1] * rQ);

            float2* H = hf ? Q3 : P3;
            H[0] = make_float2(AH, 0.f);
            H[1] = cscale(T2, AH);
            H[2] = cscale(T1, AH);
            H[3] = cmul(H[2], T2);
            H[4] = cscale(T0, AH);
            H[5] = cmul(H[4], T2);
            H[6] = cmul(H[4], T1);
            H[7] = cmul(H[6], T2);
        }

        __nv_bfloat16* arow = As + tid * AS;
        int stag = lane >> 3;   // conflict-free stagger
#pragma unroll
        for (int i = 0; i < 32; i++) {
            int j0 = (i + stag) & 31;
            int ja = 2 * j0, jb = 2 * j0 + 1;
            float2 aa = cmul(P3[ja >> 3], Q3[ja & 7]);
            float2 ab = cmul(P3[jb >> 3], Q3[jb & 7]);
            *(__nv_bfloat162*)(arow + 2 * j0) =
                __nv_bfloat162(__float2bfloat16(aa.x), __float2bfloat16(ab.x));
            *(__nv_bfloat162*)(arow + 64 + 2 * j0) =
                __nv_bfloat162(__float2bfloat16(aa.y), __float2bfloat16(ab.y));
        }
    }
    __syncthreads();

    // ---- GEMM: pair p, 2 M-tiles; this warp's N half (half*64 .. +64) ----
    float c[2][8][4];
#pragma unroll
    for (int t = 0; t < 2; t++)
#pragma unroll
        for (int nt = 0; nt < 8; nt++)
#pragma unroll
            for (int e = 0; e < 4; e++) c[t][nt][e] = 0.f;

    uint32_t asBase = (uint32_t)__cvta_generic_to_shared(As);
    uint32_t wsBase = (uint32_t)__cvta_generic_to_shared(Ws);
    uint32_t aAddr0 = asBase + (uint32_t)(((pair * 32 + (lane & 15)) * AS + ((lane >> 4) << 3)) * 2);
    uint32_t aAddr1 = aAddr0 + (uint32_t)(16 * AS * 2);
    uint32_t bAddr = wsBase + (uint32_t)(((half * 64 + (lane & 7) + ((lane >> 4) << 3)) * AS +
                                          (((lane >> 3) & 1) << 3)) * 2);

#pragma unroll
    for (int ko = 0; ko < 8; ko++) {
        uint32_t a0[4], a1[4];
        ldmx4(a0, aAddr0 + (uint32_t)(ko * 32));
        ldmx4(a1, aAddr1 + (uint32_t)(ko * 32));
#pragma unroll
        for (int n4 = 0; n4 < 4; n4++) {
            uint32_t b[4];
            ldmx4(b, bAddr + (uint32_t)(n4 * 16 * AS * 2 + ko * 32));
            mma16816(c[0][n4 * 2],     a0[0], a0[1], a0[2], a0[3], b[0], b[1]);
            mma16816(c[0][n4 * 2 + 1], a0[0], a0[1], a0[2], a0[3], b[2], b[3]);
            mma16816(c[1][n4 * 2],     a1[0], a1[1], a1[2], a1[3], b[0], b[1]);
            mma16816(c[1][n4 * 2 + 1], a1[0], a1[1], a1[2], a1[3], b[2], b[3]);
        }
    }
    __syncthreads();   // all warps done reading As; Ex may now overwrite it

    // ---- odd warps: write bi^2 into Ex[pair][lane][slot], slot = (t*8+nt)*4+e ----
    if (half == 1) {
        float* exl = Ex + (pair * 32 + lane) * 68;
#pragma unroll
        for (int t = 0; t < 2; t++)
#pragma unroll
            for (int nt = 0; nt < 8; nt++) {
                float4 sqv;
                sqv.x = c[t][nt][0] * c[t][nt][0];
                sqv.y = c[t][nt][1] * c[t][nt][1];
                sqv.z = c[t][nt][2] * c[t][nt][2];
                sqv.w = c[t][nt][3] * c[t][nt][3];
                *(float4*)(exl + (t * 8 + nt) * 4) = sqv;
            }
    }
    __syncthreads();

    // ---- even warps: probs + residual + LayerNorm into Xs ----
    if (half == 0) {
        const float* exl = Ex + (pair * 32 + lane) * 68;
#pragma unroll
        for (int t = 0; t < 2; t++) {
#pragma unroll
            for (int rh = 0; rh < 2; rh++) {
                int row = pair * 32 + t * 16 + g + rh * 8;   // CTA-local sample row
                float* Xr = Xs + row * 65;
                float v[16];
                float sum = 0.f, sq = 0.f;
#pragma unroll
                for (int nt = 0; nt < 8; nt++) {
                    int j = nt * 8 + t4 * 2;
                    float2 bi2 = *(const float2*)(exl + (t * 8 + nt) * 4 + rh * 2);
                    float x0 = Xr[j], x1 = Xr[j + 1];
                    float br0 = c[t][nt][rh * 2 + 0];
                    float br1 = c[t][nt][rh * 2 + 1];
                    float v0 = fmaf(br0, br0, bi2.x) + x0;
                    float v1 = fmaf(br1, br1, bi2.y) + x1;
                    v[nt * 2] = v0; v[nt * 2 + 1] = v1;
                    sum += v0 + v1;
                    sq = fmaf(v0, v0, fmaf(v1, v1, sq));
                }
                sum += __shfl_xor_sync(0xffffffffu, sum, 1);
                sum += __shfl_xor_sync(0xffffffffu, sum, 2);
                sq  += __shfl_xor_sync(0xffffffffu, sq, 1);
                sq  += __shfl_xor_sync(0xffffffffu, sq, 2);
                float mu = sum * (1.f / 64.f);
                float vv = sq * (1.f / 64.f) - mu * mu;
                float rstd = rsqrtf(vv + 1e-5f);
#pragma unroll
                for (int nt = 0; nt < 8; nt++) {
                    int j = nt * 8 + t4 * 2;
                    Xr[j]     = fmaf((v[nt * 2] - mu) * rstd,     gb[j],     gb[64 + j]);
                    Xr[j + 1] = fmaf((v[nt * 2 + 1] - mu) * rstd, gb[j + 1], gb[64 + j + 1]);
                }
            }
        }
    }
    __syncthreads();

    // ---- coalesced store out ----
    {
        float4* o4 = (float4*)out;
        size_t tb4 = (size_t)blockIdx.x * 2048;
        size_t lim = (size_t)nsamp * 16;
#pragma unroll
        for (int i = 0; i < 8; i++) {
            int e = tid + 256 * i;
            int row = e >> 4, cc = (e & 15) * 4;
            float* p = Xs + row * 65 + cc;
            float4 v = make_float4(p[0], p[1], p[2], p[3]);
            size_t gaddr = tb4 + e;
            if (gaddr < lim) o4[gaddr] = v;
        }
    }
}

// ---------------- launch ----------------
extern "C" void kernel_launch(void* const* d_in, const int* in_sizes, int n_in,
                              void* d_out, int out_size) {
    const float* x      = (const float*)d_in[0];
    const float* var    = (const float*)d_in[1];
    const float* gamma_ = (const float*)d_in[2];
    const float* beta_  = (const float*)d_in[3];
    float* out = (float*)d_out;

    int nsamp = in_sizes[0] / 64;

    cudaFuncSetAttribute(ffb_mma_kernel,
                         cudaFuncAttributeMaxDynamicSharedMemorySize, SMEM_DYN);

    build_W_kernel<<<64, 32>>>(var);

    int blocks = (nsamp + 127) / 128;
    ffb_mma_kernel<<<blocks, 256, SMEM_DYN>>>(x, gamma_, beta_, out, nsamp);
}

// round 15
// speedup vs baseline: 1.2923x; 1.0445x over previous
#include <cuda_runtime.h>
#include <cuda_bf16.h>
#include <math.h>
#include <stdint.h>

#define NW 6

// W: real 128x128 bf16, row-major. Row n<64 -> br_n weights; row 64+n -> bi_n.
__device__ __align__(16) __nv_bfloat16 d_W[128 * 128];

// ---------------- complex helpers ----------------
__device__ __forceinline__ float2 cmul(float2 a, float2 b) {
    return make_float2(a.x * b.x - a.y * b.y, a.x * b.y + a.y * b.x);
}
__device__ __forceinline__ float2 cadd(float2 a, float2 b) {
    return make_float2(a.x + b.x, a.y + b.y);
}
__device__ __forceinline__ float2 cscale(float2 a, float s) {
    return make_float2(a.x * s, a.y * s);
}
__device__ __forceinline__ float2 shflxor(float2 v, int m) {
    v.x = __shfl_xor_sync(0xffffffffu, v.x, m);
    v.y = __shfl_xor_sync(0xffffffffu, v.y, m);
    return v;
}

// ================= build_W (64 blocks x 32 threads) =================
__device__ __forceinline__ void apply_diag(float2& s0, float2& s1, int lane, int w,
                                           float2 d0, float2 d1) {
    int bit = 5 - w;
    if (bit == 0) {
        s0 = cmul(s0, d0);
        s1 = cmul(s1, d1);
    } else {
        int mb = (lane >> (bit - 1)) & 1;
        float2 d = mb ? d1 : d0;
        s0 = cmul(s0, d);
        s1 = cmul(s1, d);
    }
}

__device__ __forceinline__ void apply1(float2& s0, float2& s1, int lane, int w,
                                       float2 u00, float2 u01, float2 u10, float2 u11) {
    int bit = 5 - w;
    if (bit == 0) {
        float2 t0 = cadd(cmul(u00, s0), cmul(u01, s1));
        float2 t1 = cadd(cmul(u10, s0), cmul(u11, s1));
        s0 = t0; s1 = t1;
    } else {
        int lm = 1 << (bit - 1);
        float2 p0 = shflxor(s0, lm);
        float2 p1 = shflxor(s1, lm);
        int mb = (lane >> (bit - 1)) & 1;
        if (mb == 0) {
            s0 = cadd(cmul(u00, s0), cmul(u01, p0));
            s1 = cadd(cmul(u00, s1), cmul(u01, p1));
        } else {
            s0 = cadd(cmul(u10, p0), cmul(u11, s0));
            s1 = cadd(cmul(u10, p1), cmul(u11, s1));
        }
    }
}

__device__ __forceinline__ float2 bsu(float2 s, float2 p, int na, int nb,
                                      float c, float sn, float c2, float ex, float ey) {
    if (na == nb) return na ? cscale(s, c2) : s;
    if (na == 0) {
        return make_float2(c * s.x + sn * (ex * p.x - ey * p.y),
                           c * s.y + sn * (ex * p.y + ey * p.x));
    } else {
        return make_float2(c * s.x - sn * (ex * p.x + ey * p.y),
                           c * s.y - sn * (ex * p.y - ey * p.x));
    }
}

__device__ __forceinline__ void apply_bs(float2& s0, float2& s1, int lane, int w,
                                         float th, float ph) {
    float c, sn;
    __sincosf(th, &sn, &c);
    float c2 = c * c - sn * sn;
    float ex, ey;
    __sincosf(ph, &ey, &ex);
    int ba = 5 - w, bb = 4 - w;
    float2 p0, p1;
    if (bb >= 1) {
        int lm = ((1 << ba) | (1 << bb)) >> 1;
        p0 = shflxor(s0, lm);
        p1 = shflxor(s1, lm);
    } else {
        p0 = shflxor(s1, 1);
        p1 = shflxor(s0, 1);
    }
    int n0 = lane * 2, n1 = lane * 2 + 1;
    s0 = bsu(s0, p0, (n0 >> ba) & 1, (n0 >> bb) & 1, c, sn, c2, ex, ey);
    s1 = bsu(s1, p1, (n1 >> ba) & 1, (n1 >> bb) & 1, c, sn, c2, ex, ey);
}

__global__ void build_W_kernel(const float* __restrict__ var) {
    int col = blockIdx.x;
    int lane = threadIdx.x;
    float2 s0 = make_float2(0.f, 0.f), s1 = make_float2(0.f, 0.f);
    if (lane * 2 == col) s0.x = 1.f;
    if (lane * 2 + 1 == col) s1.x = 1.f;

    for (int l = 0; l < 2; l++) {
        const float* v = var + 50 * l;
        for (int i = 0; i < 5; i++)
            apply_bs(s0, s1, lane, i, __ldg(v + 2 * i), __ldg(v + 2 * i + 1));
        for (int w = 0; w < NW; w++) {
            float ph = __ldg(v + 10 + w);
            float sp, cp; __sincosf(ph, &sp, &cp);
            apply_diag(s0, s1, lane, w, make_float2(1.f, 0.f), make_float2(cp, sp));
        }
        for (int w = 0; w < NW; w++) {
            float r = __ldg(v + 16 + w);
            float e = __expf(r);
            float sech = __fdividef(2.f * e, fmaf(e, e, 1.f));
            float sr = sqrtf(sech);
            apply_diag(s0, s1, lane, w, make_float2(sr, 0.f), make_float2(sech * sr, 0.f));
        }
        for (int i = 0; i < 5; i++)
            apply_bs(s0, s1, lane, i, __ldg(v + 22 + 2 * i), __ldg(v + 23 + 2 * i));
        for (int w = 0; w < NW; w++) {
            float ph = __ldg(v + 32 + w);
            float sp, cp; __sincosf(ph, &sp, &cp);
            apply_diag(s0, s1, lane, w, make_float2(1.f, 0.f), make_float2(cp, sp));
        }
        for (int w = 0; w < NW; w++) {
            float r = __ldg(v + 38 + w);
            float pref = __expf(-0.5f * r * r);
            apply1(s0, s1, lane, w,
                   make_float2(pref, 0.f), make_float2(-pref * r, 0.f),
                   make_float2(pref * r, 0.f), make_float2(pref * (1.f - r * r), 0.f));
        }
        for (int w = 0; w < NW; w++) {
            float ph = __ldg(v + 44 + w);
            float sp, cp; __sincosf(ph, &sp, &cp);
            apply_diag(s0, s1, lane, w, make_float2(1.f, 0.f), make_float2(cp, sp));
        }
    }
    int k = col;
#pragma unroll
    for (int h = 0; h < 2; h++) {
        float2 u = h ? s1 : s0;
        int r = 2 * lane + h;
        d_W[r * 128 + k]              = __float2bfloat16(u.x);
        d_W[r * 128 + 64 + k]         = __float2bfloat16(-u.y);
        d_W[(64 + r) * 128 + k]       = __float2bfloat16(u.y);
        d_W[(64 + r) * 128 + 64 + k]  = __float2bfloat16(u.x);
    }
}

// ================= main fused kernel =================
// 256 threads/CTA, 128 samples/CTA, 8 warps x 16 samples, 2 CTAs/SM.
// Prologue split across 2 threads/sample (P half: wires 0-2, Q half: wires 3-5);
// minimal halves exchanged via PQ scratch overlaid on the A region.
// Epilogue stores LN output directly to global (sector-perfect float2).
// smem: A 128x136 bf16 [0,34816) (PQ scratch overlays [0,13312) pre-A) ;
//       Ws 128x136 bf16 [34816,69632) ; Xs 128x65 f32 [69632,102912) ; gb 128 f32.

static constexpr int AS = 136;                        // A row stride, bf16 units
static constexpr int PQS = 26;                        // PQ sample stride, floats
static constexpr uint32_t W_OFF  = 128u * AS * 2u;    // 34816
static constexpr uint32_t X_OFF  = W_OFF * 2u;        // 69632
static constexpr uint32_t GB_OFF = X_OFF + 128u * 65u * 4u;  // 102912
static constexpr uint32_t SMEM_DYN = GB_OFF + 512u;   // 103424

__device__ __forceinline__ void mma16816(float c[4], uint32_t a0, uint32_t a1,
                                         uint32_t a2, uint32_t a3,
                                         uint32_t b0, uint32_t b1) {
    asm("mma.sync.aligned.m16n8k16.row.col.f32.bf16.bf16.f32 "
        "{%0,%1,%2,%3}, {%4,%5,%6,%7}, {%8,%9}, {%0,%1,%2,%3};"
        : "+f"(c[0]), "+f"(c[1]), "+f"(c[2]), "+f"(c[3])
        : "r"(a0), "r"(a1), "r"(a2), "r"(a3), "r"(b0), "r"(b1));
}

__device__ __forceinline__ void ldmx4(uint32_t r[4], uint32_t addr) {
    asm volatile("ldmatrix.sync.aligned.m8n8.x4.shared.b16 {%0,%1,%2,%3}, [%4];"
                 : "=r"(r[0]), "=r"(r[1]), "=r"(r[2]), "=r"(r[3]) : "r"(addr));
}

__global__ void __launch_bounds__(256, 2)
ffb_mma_kernel(const float* __restrict__ x,
               const float* __restrict__ gamma_, const float* __restrict__ beta_,
               float* __restrict__ out, int nsamp) {
    extern __shared__ __align__(16) unsigned char dsm[];
    __nv_bfloat16* As = (__nv_bfloat16*)(dsm);
    float* PQ         = (float*)(dsm);                 // overlays A region pre-A-write
    __nv_bfloat16* Ws = (__nv_bfloat16*)(dsm + W_OFF);
    float* Xs         = (float*)(dsm + X_OFF);
    float* gb         = (float*)(dsm + GB_OFF);

    int tid  = threadIdx.x;
    int wid  = tid >> 5;
    int lane = tid & 31;
    int g    = lane >> 2;
    int t4   = lane & 3;

    // ---- stage x tile (coalesced float4) into padded Xs ----
    {
        const float4* x4 = (const float4*)x;
        size_t tb4 = (size_t)blockIdx.x * 2048;
        size_t lim = (size_t)nsamp * 16;
#pragma unroll
        for (int i = 0; i < 8; i++) {
            int e = tid + 256 * i;
            size_t gaddr = tb4 + e;
            float4 v = (gaddr < lim) ? __ldg(x4 + gaddr) : make_float4(0.f, 0.f, 0.f, 0.f);
            int row = e >> 4, c = (e & 15) * 4;
            float* p = Xs + row * 65 + c;
            p[0] = v.x; p[1] = v.y; p[2] = v.z; p[3] = v.w;
        }
    }
    // ---- stage W (coalesced) into padded Ws ----
    {
        const float4* src = (const float4*)d_W;
#pragma unroll
        for (int i = 0; i < 8; i++) {
            int e = tid + 256 * i;
            int row = e >> 4, c = e & 15;
            *(float4*)(Ws + row * AS + c * 8) = __ldg(src + e);
        }
    }
    if (tid < 16)      ((float4*)gb)[tid] = ((const float4*)gamma_)[tid];
    else if (tid < 32) ((float4*)gb)[tid] = ((const float4*)beta_)[tid - 16];
    __syncthreads();

    // ---- prologue, 2 threads per sample ----
    int srow = tid & 127;           // sample (CTA-local)
    int isQ  = tid >> 7;            // 0: wires 0-2 (P half), 1: wires 3-5 (Q half)
    float2 H[8];                    // this thread's half-products (incl. its AH)
    {
        const float* Xrow = Xs + srow * 65;
        int wb = 3 * isQ;
        float e2v[3], qv[3], rdv[3];
        float2 cs[3];
        float Pp = 1.f, Ep = 1.f, rdsq = 0.f;
#pragma unroll
        for (int i = 0; i < 3; i++) {
            int w = wb + i;
            float r1   = Xrow[2 * w];
            float rd   = Xrow[28 + 2 * w];
            float phid = Xrow[29 + 2 * w];
            float phik = Xrow[40 + w];
            float r2   = Xrow[46 + 2 * w];
            float phir = Xrow[58 + w];
            float e1 = __expf(r1);
            float e2 = __expf(r2);
            e2v[i] = e2;
            qv[i] = fmaf(e2, e2, 1.f);
            Pp *= fmaf(e1, e1, 1.f);
            Ep *= e1 * e2;
            rdv[i] = rd;
            rdsq = fmaf(rd, rd, rdsq);
            float th = phid + phik + phir;
            float sth, cth;
            __sincosf(th, &sth, &cth);
            cs[i] = make_float2(cth, sth);
        }
        float prefH = __expf(-0.5f * rdsq);
        float Qp = qv[0] * qv[1] * qv[2];
        float rQ  = __fdividef(1.f, Qp);
        float rPQ = __fdividef(1.f, Pp * Qp);
        float sH = 64.f * Ep * rPQ;                    // prod sech1*sech2 over 3 wires
        float AH = prefH * sqrtf(sH);
        float2 T0 = cscale(cs[0], rdv[0] * 2.f * e2v[0] * qv[1] * qv[2] * rQ);
        float2 T1 = cscale(cs[1], rdv[1] * 2.f * e2v[1] * qv[0] * qv[2] * rQ);
        float2 T2 = cscale(cs[2], rdv[2] * 2.f * e2v[2] * qv[0] * qv[1] * rQ);

        H[0] = make_float2(AH, 0.f);
        H[1] = cscale(T2, AH);
        H[2] = cscale(T1, AH);
        H[3] = cmul(H[2], T2);
        H[4] = cscale(T0, AH);
        H[5] = cmul(H[4], T2);
        H[6] = cmul(H[4], T1);
        H[7] = cmul(H[6], T2);
    }
    // exchange: PQ[sample][0..7] = Q3 (from Q thread), [8..11] = P3[4..7] (from P thread)
    {
        float2* base = (float2*)(PQ + srow * PQS);
        if (isQ) {
#pragma unroll
            for (int k = 0; k < 8; k++) base[k] = H[k];
        } else {
#pragma unroll
            for (int k = 0; k < 4; k++) base[8 + k] = H[4 + k];
        }
    }
    __syncthreads();
    float2 Ox[8];    // partner data: P thread -> Q3[0..7]; Q thread -> P3[4..7] in Ox[0..3]
    {
        float2* base = (float2*)(PQ + srow * PQS);
        if (isQ) {
#pragma unroll
            for (int k = 0; k < 4; k++) Ox[k] = base[8 + k];
        } else {
#pragma unroll
            for (int k = 0; k < 8; k++) Ox[k] = base[k];
        }
    }
    __syncthreads();   // PQ reads complete; A writes may now overwrite the region

    // ---- write this thread's half of A row srow (16 column-pairs) ----
    {
        __nv_bfloat16* arow = As + srow * AS;
        int stag = lane >> 3;
#pragma unroll
        for (int i = 0; i < 16; i++) {
            int j0 = ((i + stag) & 15) + isQ * 16;     // column pair index 0..31
            int ja = 2 * j0;
            float2 aa, ab;
            if (isQ) {  // P from Ox[(ja>>3)-4], Q local H[ja&7]
                float2 Pv = Ox[(ja >> 3) - 4];
                aa = cmul(Pv, H[ja & 7]);
                ab = cmul(Pv, H[(ja & 7) + 1]);
            } else {    // P local H[ja>>3], Q from Ox[ja&7]
                float2 Pv = H[ja >> 3];
                aa = cmul(Pv, Ox[ja & 7]);
                ab = cmul(Pv, Ox[(ja & 7) + 1]);
            }
            *(__nv_bfloat162*)(arow + 2 * j0) =
                __nv_bfloat162(__float2bfloat16(aa.x), __float2bfloat16(ab.x));
            *(__nv_bfloat162*)(arow + 64 + 2 * j0) =
                __nv_bfloat162(__float2bfloat16(aa.y), __float2bfloat16(ab.y));
        }
    }
    __syncthreads();

    // ---- GEMM: warp computes C[16 x 128] for samples [wid*16, wid*16+16) ----
    int warpM = wid * 16;
    float c[16][4];
#pragma unroll
    for (int nt = 0; nt < 16; nt++)
#pragma unroll
        for (int e = 0; e < 4; e++) c[nt][e] = 0.f;

    uint32_t asBase = (uint32_t)__cvta_generic_to_shared(As);
    uint32_t wsBase = (uint32_t)__cvta_generic_to_shared(Ws);
    uint32_t aAddr = asBase + (uint32_t)(((warpM + (lane & 15)) * AS + ((lane >> 4) << 3)) * 2);
    uint32_t bAddr = wsBase + (uint32_t)(((((lane & 7) + ((lane >> 4) << 3)) * AS) +
                                          (((lane >> 3) & 1) << 3)) * 2);

#pragma unroll
    for (int ko = 0; ko < 8; ko++) {
        uint32_t a[4];
        ldmx4(a, aAddr + (uint32_t)(ko * 32));
#pragma unroll
        for (int nt2 = 0; nt2 < 8; nt2++) {
            uint32_t b[4];
            ldmx4(b, bAddr + (uint32_t)(nt2 * 16 * AS * 2 + ko * 32));
            mma16816(c[nt2 * 2],     a[0], a[1], a[2], a[3], b[0], b[1]);
            mma16816(c[nt2 * 2 + 1], a[0], a[1], a[2], a[3], b[2], b[3]);
        }
    }

    // ---- epilogue: probs + residual + LayerNorm, direct global store ----
    int blockBase = blockIdx.x * 128;
#pragma unroll
    for (int half = 0; half < 2; half++) {
        int rowL = warpM + g + half * 8;             // CTA-local sample row
        float* Xr = Xs + rowL * 65;
        float sum = 0.f, sq = 0.f;
#pragma unroll
        for (int nt = 0; nt < 8; nt++) {
            int j = nt * 8 + t4 * 2;
            float x0 = Xr[j], x1 = Xr[j + 1];
            float br0 = c[nt][half * 2 + 0];
            float bi0 = c[nt + 8][half * 2 + 0];
            float br1 = c[nt][half * 2 + 1];
            float bi1 = c[nt + 8][half * 2 + 1];
            float v0 = fmaf(br0, br0, bi0 * bi0) + x0;
            float v1 = fmaf(br1, br1, bi1 * bi1) + x1;
            c[nt][half * 2 + 0] = v0;
            c[nt][half * 2 + 1] = v1;
            sum += v0 + v1;
            sq = fmaf(v0, v0, fmaf(v1, v1, sq));
        }
        sum += __shfl_xor_sync(0xffffffffu, sum, 1);
        sum += __shfl_xor_sync(0xffffffffu, sum, 2);
        sq  += __shfl_xor_sync(0xffffffffu, sq, 1);
        sq  += __shfl_xor_sync(0xffffffffu, sq, 2);
        float mu = sum * (1.f / 64.f);
        float vv = sq * (1.f / 64.f) - mu * mu;
        float rstd = rsqrtf(vv + 1e-5f);
        int rowG = blockBase + rowL;
        if (rowG < nsamp) {
            float* orow = out + (size_t)rowG * 64;
#pragma unroll
            for (int nt = 0; nt < 8; nt++) {
                int j = nt * 8 + t4 * 2;
                float2 ov;
                ov.x = fmaf((c[nt][half * 2 + 0] - mu) * rstd, gb[j],     gb[64 + j]);
                ov.y = fmaf((c[nt][half * 2 + 1] - mu) * rstd, gb[j + 1], gb[64 + j + 1]);
                *(float2*)(orow + j) = ov;
            }
        }
    }
}

// ---------------- launch ----------------
extern "C" void kernel_launch(void* const* d_in, const int* in_sizes, int n_in,
                              void* d_out, int out_size) {
    const float* x      = (const float*)d_in[0];
    const float* var    = (const float*)d_in[1];
    const float* gamma_ = (const float*)d_in[2];
    const float* beta_  = (const float*)d_in[3];
    float* out = (float*)d_out;

    int nsamp = in_sizes[0] / 64;

    cudaFuncSetAttribute(ffb_mma_kernel,
                         cudaFuncAttributeMaxDynamicSharedMemorySize, SMEM_DYN);

    build_W_kernel<<<64, 32>>>(var);

    int blocks = (nsamp + 127) / 128;
    ffb_mma_kernel<<<blocks, 256, SMEM_DYN>>>(x, gamma_, beta_, out, nsamp);
}

// round 16
// speedup vs baseline: 1.4396x; 1.1139x over previous
#include <cuda_runtime.h>
#include <cuda_bf16.h>
#include <math.h>
#include <stdint.h>

#define NW 6

// U = Ur + i*Ui, 64x64 bf16 each, row-major [row*64 + col].
__device__ __align__(16) __nv_bfloat16 d_Ur[64 * 64];
__device__ __align__(16) __nv_bfloat16 d_Ui[64 * 64];

// ---------------- complex helpers ----------------
__device__ __forceinline__ float2 cmul(float2 a, float2 b) {
    return make_float2(a.x * b.x - a.y * b.y, a.x * b.y + a.y * b.x);
}
__device__ __forceinline__ float2 cadd(float2 a, float2 b) {
    return make_float2(a.x + b.x, a.y + b.y);
}
__device__ __forceinline__ float2 cscale(float2 a, float s) {
    return make_float2(a.x * s, a.y * s);
}
__device__ __forceinline__ float2 shflxor(float2 v, int m) {
    v.x = __shfl_xor_sync(0xffffffffu, v.x, m);
    v.y = __shfl_xor_sync(0xffffffffu, v.y, m);
    return v;
}

// ================= build_U (64 blocks x 32 threads) =================
__device__ __forceinline__ void apply_diag(float2& s0, float2& s1, int lane, int w,
                                           float2 d0, float2 d1) {
    int bit = 5 - w;
    if (bit == 0) {
        s0 = cmul(s0, d0);
        s1 = cmul(s1, d1);
    } else {
        int mb = (lane >> (bit - 1)) & 1;
        float2 d = mb ? d1 : d0;
        s0 = cmul(s0, d);
        s1 = cmul(s1, d);
    }
}

__device__ __forceinline__ void apply1(float2& s0, float2& s1, int lane, int w,
                                       float2 u00, float2 u01, float2 u10, float2 u11) {
    int bit = 5 - w;
    if (bit == 0) {
        float2 t0 = cadd(cmul(u00, s0), cmul(u01, s1));
        float2 t1 = cadd(cmul(u10, s0), cmul(u11, s1));
        s0 = t0; s1 = t1;
    } else {
        int lm = 1 << (bit - 1);
        float2 p0 = shflxor(s0, lm);
        float2 p1 = shflxor(s1, lm);
        int mb = (lane >> (bit - 1)) & 1;
        if (mb == 0) {
            s0 = cadd(cmul(u00, s0), cmul(u01, p0));
            s1 = cadd(cmul(u00, s1), cmul(u01, p1));
        } else {
            s0 = cadd(cmul(u10, p0), cmul(u11, s0));
            s1 = cadd(cmul(u10, p1), cmul(u11, s1));
        }
    }
}

__device__ __forceinline__ float2 bsu(float2 s, float2 p, int na, int nb,
                                      float c, float sn, float c2, float ex, float ey) {
    if (na == nb) return na ? cscale(s, c2) : s;
    if (na == 0) {
        return make_float2(c * s.x + sn * (ex * p.x - ey * p.y),
                           c * s.y + sn * (ex * p.y + ey * p.x));
    } else {
        return make_float2(c * s.x - sn * (ex * p.x + ey * p.y),
                           c * s.y - sn * (ex * p.y - ey * p.x));
    }
}

__device__ __forceinline__ void apply_bs(float2& s0, float2& s1, int lane, int w,
                                         float th, float ph) {
    float c, sn;
    __sincosf(th, &sn, &c);
    float c2 = c * c - sn * sn;
    float ex, ey;
    __sincosf(ph, &ey, &ex);
    int ba = 5 - w, bb = 4 - w;
    float2 p0, p1;
    if (bb >= 1) {
        int lm = ((1 << ba) | (1 << bb)) >> 1;
        p0 = shflxor(s0, lm);
        p1 = shflxor(s1, lm);
    } else {
        p0 = shflxor(s1, 1);
        p1 = shflxor(s0, 1);
    }
    int n0 = lane * 2, n1 = lane * 2 + 1;
    s0 = bsu(s0, p0, (n0 >> ba) & 1, (n0 >> bb) & 1, c, sn, c2, ex, ey);
    s1 = bsu(s1, p1, (n1 >> ba) & 1, (n1 >> bb) & 1, c, sn, c2, ex, ey);
}

__global__ void build_W_kernel(const float* __restrict__ var) {
    int col = blockIdx.x;
    int lane = threadIdx.x;
    float2 s0 = make_float2(0.f, 0.f), s1 = make_float2(0.f, 0.f);
    if (lane * 2 == col) s0.x = 1.f;
    if (lane * 2 + 1 == col) s1.x = 1.f;

    for (int l = 0; l < 2; l++) {
        const float* v = var + 50 * l;
        for (int i = 0; i < 5; i++)
            apply_bs(s0, s1, lane, i, __ldg(v + 2 * i), __ldg(v + 2 * i + 1));
        for (int w = 0; w < NW; w++) {
            float ph = __ldg(v + 10 + w);
            float sp, cp; __sincosf(ph, &sp, &cp);
            apply_diag(s0, s1, lane, w, make_float2(1.f, 0.f), make_float2(cp, sp));
        }
        for (int w = 0; w < NW; w++) {
            float r = __ldg(v + 16 + w);
            float e = __expf(r);
            float sech = __fdividef(2.f * e, fmaf(e, e, 1.f));
            float sr = sqrtf(sech);
            apply_diag(s0, s1, lane, w, make_float2(sr, 0.f), make_float2(sech * sr, 0.f));
        }
        for (int i = 0; i < 5; i++)
            apply_bs(s0, s1, lane, i, __ldg(v + 22 + 2 * i), __ldg(v + 23 + 2 * i));
        for (int w = 0; w < NW; w++) {
            float ph = __ldg(v + 32 + w);
            float sp, cp; __sincosf(ph, &sp, &cp);
            apply_diag(s0, s1, lane, w, make_float2(1.f, 0.f), make_float2(cp, sp));
        }
        for (int w = 0; w < NW; w++) {
            float r = __ldg(v + 38 + w);
            float pref = __expf(-0.5f * r * r);
            apply1(s0, s1, lane, w,
                   make_float2(pref, 0.f), make_float2(-pref * r, 0.f),
                   make_float2(pref * r, 0.f), make_float2(pref * (1.f - r * r), 0.f));
        }
        for (int w = 0; w < NW; w++) {
            float ph = __ldg(v + 44 + w);
            float sp, cp; __sincosf(ph, &sp, &cp);
            apply_diag(s0, s1, lane, w, make_float2(1.f, 0.f), make_float2(cp, sp));
        }
    }
    int k = col;
#pragma unroll
    for (int h = 0; h < 2; h++) {
        float2 u = h ? s1 : s0;
        int r = 2 * lane + h;
        d_Ur[r * 64 + k] = __float2bfloat16(u.x);
        d_Ui[r * 64 + k] = __float2bfloat16(u.y);
    }
}

// ================= main fused kernel =================
// 256 threads/CTA, 128 samples/CTA, 8 warps x 16 samples, 2 CTAs/SM.
// Karatsuba-style: br = ar*Ur^T - ai*Ui^T, bi = ar*Ui^T + ai*Ur^T.
// Each Ur/Ui fragment serves 2 MMAs -> B-ldmatrix traffic halved.
// smem layout (bytes):
//   Ar 128x72 bf16 [0,18432) ; Ai 128x72 bf16 [18432,36864) ;
//   Urs 64x72 bf16 [36864,46080) ; Uis 64x72 bf16 [46080,55296) ;
//   Xs 128x65 f32 [55296,88576) ; gb 128 f32 [88576,89088).

static constexpr int AS2 = 72;                         // row stride, bf16 units
static constexpr uint32_t AI_OFF = 128u * AS2 * 2u;    // 18432
static constexpr uint32_t UR_OFF = AI_OFF * 2u;        // 36864
static constexpr uint32_t UI_OFF = UR_OFF + 64u * AS2 * 2u;   // 46080
static constexpr uint32_t X_OFF  = UI_OFF + 64u * AS2 * 2u;   // 55296
static constexpr uint32_t GB_OFF = X_OFF + 128u * 65u * 4u;   // 88576
static constexpr uint32_t SMEM_DYN = GB_OFF + 512u;    // 89088

__device__ __forceinline__ void mma16816(float c[4], const uint32_t a[4],
                                         uint32_t b0, uint32_t b1) {
    asm("mma.sync.aligned.m16n8k16.row.col.f32.bf16.bf16.f32 "
        "{%0,%1,%2,%3}, {%4,%5,%6,%7}, {%8,%9}, {%0,%1,%2,%3};"
        : "+f"(c[0]), "+f"(c[1]), "+f"(c[2]), "+f"(c[3])
        : "r"(a[0]), "r"(a[1]), "r"(a[2]), "r"(a[3]), "r"(b0), "r"(b1));
}

__device__ __forceinline__ void ldmx4(uint32_t r[4], uint32_t addr) {
    asm volatile("ldmatrix.sync.aligned.m8n8.x4.shared.b16 {%0,%1,%2,%3}, [%4];"
                 : "=r"(r[0]), "=r"(r[1]), "=r"(r[2]), "=r"(r[3]) : "r"(addr));
}

__global__ void __launch_bounds__(256, 2)
ffb_mma_kernel(const float* __restrict__ x,
               const float* __restrict__ gamma_, const float* __restrict__ beta_,
               float* __restrict__ out, int nsamp) {
    extern __shared__ __align__(16) unsigned char dsm[];
    __nv_bfloat16* Ar  = (__nv_bfloat16*)(dsm);
    __nv_bfloat16* Ai  = (__nv_bfloat16*)(dsm + AI_OFF);
    __nv_bfloat16* Urs = (__nv_bfloat16*)(dsm + UR_OFF);
    __nv_bfloat16* Uis = (__nv_bfloat16*)(dsm + UI_OFF);
    float* Xs          = (float*)(dsm + X_OFF);
    float* gb          = (float*)(dsm + GB_OFF);

    int tid  = threadIdx.x;
    int wid  = tid >> 5;
    int lane = tid & 31;
    int g    = lane >> 2;
    int t4   = lane & 3;

    // ---- stage x tile (coalesced float4) into padded Xs ----
    {
        const float4* x4 = (const float4*)x;
        size_t tb4 = (size_t)blockIdx.x * 2048;
        size_t lim = (size_t)nsamp * 16;
#pragma unroll
        for (int i = 0; i < 8; i++) {
            int e = tid + 256 * i;
            size_t gaddr = tb4 + e;
            float4 v = (gaddr < lim) ? __ldg(x4 + gaddr) : make_float4(0.f, 0.f, 0.f, 0.f);
            int row = e >> 4, c = (e & 15) * 4;
            float* p = Xs + row * 65 + c;
            p[0] = v.x; p[1] = v.y; p[2] = v.z; p[3] = v.w;
        }
    }
    // ---- stage Ur, Ui (coalesced): 512 float4 each; row = e>>3, col = e&7 ----
    {
        const float4* srcR = (const float4*)d_Ur;
        const float4* srcI = (const float4*)d_Ui;
#pragma unroll
        for (int i = 0; i < 2; i++) {
            int e = tid + 256 * i;
            int row = e >> 3, c = e & 7;
            *(float4*)(Urs + row * AS2 + c * 8) = __ldg(srcR + e);
            *(float4*)(Uis + row * AS2 + c * 8) = __ldg(srcI + e);
        }
    }
    if (tid < 16)      ((float4*)gb)[tid] = ((const float4*)gamma_)[tid];
    else if (tid < 32) ((float4*)gb)[tid] = ((const float4*)beta_)[tid - 16];
    __syncthreads();

    // ---- prologue (tid<128): amplitudes from Xs -> Ar/Ai rows ----
    if (tid < 128) {
        const float* Xrow = Xs + tid * 65;
        float2 P3[8], Q3[8];

#pragma unroll
        for (int hf = 0; hf < 2; hf++) {
            int wb = 3 * hf;
            float e2v[3], qv[3], rdv[3];
            float2 cs[3];
            float Pp = 1.f, Ep = 1.f, rdsq = 0.f;
#pragma unroll
            for (int i = 0; i < 3; i++) {
                int w = wb + i;
                float r1   = Xrow[2 * w];
                float rd   = Xrow[28 + 2 * w];
                float phid = Xrow[29 + 2 * w];
                float phik = Xrow[40 + w];
                float r2   = Xrow[46 + 2 * w];
                float phir = Xrow[58 + w];
                float e1 = __expf(r1);
                float e2 = __expf(r2);
                e2v[i] = e2;
                qv[i] = fmaf(e2, e2, 1.f);
                Pp *= fmaf(e1, e1, 1.f);
                Ep *= e1 * e2;
                rdv[i] = rd;
                rdsq = fmaf(rd, rd, rdsq);
                float th = phid + phik + phir;
                float sth, cth;
                __sincosf(th, &sth, &cth);
                cs[i] = make_float2(cth, sth);
            }
            float prefH = __expf(-0.5f * rdsq);
            float Qp = qv[0] * qv[1] * qv[2];
            float rQ  = __fdividef(1.f, Qp);
            float rPQ = __fdividef(1.f, Pp * Qp);
            float sH = 64.f * Ep * rPQ;                  // prod sech1*sech2
            float AH = prefH * sqrtf(sH);
            float2 T0 = cscale(cs[0], rdv[0] * 2.f * e2v[0] * qv[1] * qv[2] * rQ);
            float2 T1 = cscale(cs[1], rdv[1] * 2.f * e2v[1] * qv[0] * qv[2] * rQ);
            float2 T2 = cscale(cs[2], rdv[2] * 2.f * e2v[2] * qv[0] * qv[1] * rQ);

            float2* H = hf ? Q3 : P3;
            H[0] = make_float2(AH, 0.f);
            H[1] = cscale(T2, AH);
            H[2] = cscale(T1, AH);
            H[3] = cmul(H[2], T2);
            H[4] = cscale(T0, AH);
            H[5] = cmul(H[4], T2);
            H[6] = cmul(H[4], T1);
            H[7] = cmul(H[6], T2);
        }

        __nv_bfloat16* arowR = Ar + tid * AS2;
        __nv_bfloat16* arowI = Ai + tid * AS2;
        int stag = lane >> 3;   // conflict-free stagger (stride-72 rows)
#pragma unroll
        for (int i = 0; i < 32; i++) {
            int j0 = (i + stag) & 31;
            int ja = 2 * j0, jb = 2 * j0 + 1;
            float2 aa = cmul(P3[ja >> 3], Q3[ja & 7]);
            float2 ab = cmul(P3[jb >> 3], Q3[jb & 7]);
            *(__nv_bfloat162*)(arowR + 2 * j0) =
                __nv_bfloat162(__float2bfloat16(aa.x), __float2bfloat16(ab.x));
            *(__nv_bfloat162*)(arowI + 2 * j0) =
                __nv_bfloat162(__float2bfloat16(aa.y), __float2bfloat16(ab.y));
        }
    }
    __syncthreads();

    // ---- GEMM: warp computes br/bi [16 x 64] for samples [wid*16, wid*16+16) ----
    int warpM = wid * 16;
    float cbr[8][4], cbi[8][4];
#pragma unroll
    for (int nt = 0; nt < 8; nt++)
#pragma unroll
        for (int e = 0; e < 4; e++) { cbr[nt][e] = 0.f; cbi[nt][e] = 0.f; }

    uint32_t arBase = (uint32_t)__cvta_generic_to_shared(Ar);
    uint32_t aiBase = (uint32_t)__cvta_generic_to_shared(Ai);
    uint32_t urBase = (uint32_t)__cvta_generic_to_shared(Urs);
    uint32_t uiBase = (uint32_t)__cvta_generic_to_shared(Uis);
    uint32_t aoff = (uint32_t)(((warpM + (lane & 15)) * AS2 + ((lane >> 4) << 3)) * 2);
    uint32_t boff = (uint32_t)(((((lane & 7) + ((lane >> 4) << 3)) * AS2) +
                                (((lane >> 3) & 1) << 3)) * 2);
    uint32_t aAddrR = arBase + aoff;
    uint32_t aAddrI = aiBase + aoff;
    uint32_t bAddrR = urBase + boff;
    uint32_t bAddrI = uiBase + boff;

#pragma unroll
    for (int ko = 0; ko < 4; ko++) {
        uint32_t ar[4], ai[4], nai[4];
        ldmx4(ar, aAddrR + (uint32_t)(ko * 32));
        ldmx4(ai, aAddrI + (uint32_t)(ko * 32));
#pragma unroll
        for (int j = 0; j < 4; j++) nai[j] = ai[j] ^ 0x80008000u;
#pragma unroll
        for (int nt2 = 0; nt2 < 4; nt2++) {
            uint32_t ur[4], ui[4];
            uint32_t toff = (uint32_t)(nt2 * 16 * AS2 * 2 + ko * 32);
            ldmx4(ur, bAddrR + toff);
            ldmx4(ui, bAddrI + toff);
            mma16816(cbr[nt2 * 2],     ar,  ur[0], ur[1]);
            mma16816(cbr[nt2 * 2 + 1], ar,  ur[2], ur[3]);
            mma16816(cbr[nt2 * 2],     nai, ui[0], ui[1]);
            mma16816(cbr[nt2 * 2 + 1], nai, ui[2], ui[3]);
            mma16816(cbi[nt2 * 2],     ar,  ui[0], ui[1]);
            mma16816(cbi[nt2 * 2 + 1], ar,  ui[2], ui[3]);
            mma16816(cbi[nt2 * 2],     ai,  ur[0], ur[1]);
            mma16816(cbi[nt2 * 2 + 1], ai,  ur[2], ur[3]);
        }
    }

    // ---- epilogue: probs + residual + LayerNorm, write into Xs ----
#pragma unroll
    for (int half = 0; half < 2; half++) {
        int row = warpM + g + half * 8;
        float* Xr = Xs + row * 65;
        float sum = 0.f, sq = 0.f;
#pragma unroll
        for (int nt = 0; nt < 8; nt++) {
            int j = nt * 8 + t4 * 2;
            float x0 = Xr[j], x1 = Xr[j + 1];
            float br0 = cbr[nt][half * 2 + 0];
            float bi0 = cbi[nt][half * 2 + 0];
            float br1 = cbr[nt][half * 2 + 1];
            float bi1 = cbi[nt][half * 2 + 1];
            float v0 = fmaf(br0, br0, bi0 * bi0) + x0;
            float v1 = fmaf(br1, br1, bi1 * bi1) + x1;
            cbr[nt][half * 2 + 0] = v0;
            cbr[nt][half * 2 + 1] = v1;
            sum += v0 + v1;
            sq = fmaf(v0, v0, fmaf(v1, v1, sq));
        }
        sum += __shfl_xor_sync(0xffffffffu, sum, 1);
        sum += __shfl_xor_sync(0xffffffffu, sum, 2);
        sq  += __shfl_xor_sync(0xffffffffu, sq, 1);
        sq  += __shfl_xor_sync(0xffffffffu, sq, 2);
        float mu = sum * (1.f / 64.f);
        float vv = sq * (1.f / 64.f) - mu * mu;
        float rstd = rsqrtf(vv + 1e-5f);
#pragma unroll
        for (int nt = 0; nt < 8; nt++) {
            int j = nt * 8 + t4 * 2;
            Xr[j]     = fmaf((cbr[nt][half * 2 + 0] - mu) * rstd, gb[j],     gb[64 + j]);
            Xr[j + 1] = fmaf((cbr[nt][half * 2 + 1] - mu) * rstd, gb[j + 1], gb[64 + j + 1]);
        }
    }
    __syncthreads();

    // ---- coalesced store out ----
    {
        float4* o4 = (float4*)out;
        size_t tb4 = (size_t)blockIdx.x * 2048;
        size_t lim = (size_t)nsamp * 16;
#pragma unroll
        for (int i = 0; i < 8; i++) {
            int e = tid + 256 * i;
            int row = e >> 4, cc = (e & 15) * 4;
            float* p = Xs + row * 65 + cc;
            float4 v = make_float4(p[0], p[1], p[2], p[3]);
            size_t gaddr = tb4 + e;
            if (gaddr < lim) o4[gaddr] = v;
        }
    }
}

// ---------------- launch ----------------
extern "C" void kernel_launch(void* const* d_in, const int* in_sizes, int n_in,
                              void* d_out, int out_size) {
    const float* x      = (const float*)d_in[0];
    const float* var    = (const float*)d_in[1];
    const float* gamma_ = (const float*)d_in[2];
    const float* beta_  = (const float*)d_in[3];
    float* out = (float*)d_out;

    int nsamp = in_sizes[0] / 64;

    cudaFuncSetAttribute(ffb_mma_kernel,
                         cudaFuncAttributeMaxDynamicSharedMemorySize, SMEM_DYN);

    build_W_kernel<<<64, 32>>>(var);

    int blocks = (nsamp + 127) / 128;
    ffb_mma_kernel<<<blocks, 256, SMEM_DYN>>>(x, gamma_, beta_, out, nsamp);
}